// round 2
// baseline (speedup 1.0000x reference)
#include <cuda_runtime.h>

#define L_TOT 16384

// ---------------- device scratch (no allocations allowed) ----------------
__device__ float g_xTp[130 * 130 * 256];   // padded, location-major x: [hp][wp][b*32+i]
__device__ float g_hP[L_TOT * 16];         // per-location hidden vector for pointwise MLP
__device__ float g_kD[L_TOT * 9];          // per-location depthwise 3x3 kernel
__device__ float g_W2Pt[16 * 1024];        // W2P transposed: [h][o*32+i]
__device__ float g_kP0t[1024];             // (kernel_P + b2P) transposed: [o*32+i]

// ---------------- kernel: zero the padded border of xTp ----------------
__global__ void k_border() {
    int bid = blockIdx.x;
    int hp, wp;
    if (bid < 130)      { hp = 0;             wp = bid; }
    else if (bid < 260) { hp = 129;           wp = bid - 130; }
    else if (bid < 388) { hp = bid - 260 + 1; wp = 0; }
    else                { hp = bid - 388 + 1; wp = 129; }
    g_xTp[(hp * 130 + wp) * 256 + threadIdx.x] = 0.0f;
}

// ---------------- kernel: tiled transpose x(BC,HW) -> xTp(HW_padded, BC) ----------------
__global__ void k_transpose(const float* __restrict__ x) {
    __shared__ float tile[32][33];
    int tx = threadIdx.x & 31, ty = threadIdx.x >> 5;
    int hw0 = blockIdx.x * 32;   // 512 blocks
    int bc0 = blockIdx.y * 32;   // 8 blocks
#pragma unroll
    for (int j = 0; j < 4; j++) {
        int bc = bc0 + ty + 8 * j;
        tile[ty + 8 * j][tx] = x[bc * L_TOT + hw0 + tx];   // coalesced read
    }
    __syncthreads();
#pragma unroll
    for (int j = 0; j < 4; j++) {
        int rr = ty + 8 * j;
        int hw = hw0 + rr;
        int h = hw >> 7, w = hw & 127;
        g_xTp[((h + 1) * 130 + (w + 1)) * 256 + bc0 + tx] = tile[tx][rr];  // coalesced write
    }
}

// ---------------- kernel: weight prep (transpose W2P, fold kernel_P + b2P) ----------------
__global__ void k_prep(const float* __restrict__ kernel_P,
                       const float* __restrict__ W2P,
                       const float* __restrict__ b2P) {
    int t = threadIdx.x;
    for (int idx = t; idx < 16384; idx += 256) {
        int hh = idx >> 10, rem = idx & 1023;
        int o = rem >> 5, i = rem & 31;
        g_W2Pt[idx] = W2P[hh * 1024 + i * 32 + o];
    }
    for (int idx = t; idx < 1024; idx += 256) {
        int o = idx >> 5, i = idx & 31;
        g_kP0t[idx] = kernel_P[i * 32 + o] + b2P[i * 32 + o];
    }
}

// ---------------- kernel: per-location MLPs -> hP, kD ----------------
__global__ void k_mlp(const float* __restrict__ kernel_D,
                      const float* __restrict__ c,
                      const float* __restrict__ W1D, const float* __restrict__ b1D,
                      const float* __restrict__ W2D, const float* __restrict__ b2D,
                      const float* __restrict__ W1P, const float* __restrict__ b1P) {
    __shared__ float s[586];
    float* sW1D = s;        // 192
    float* sb1D = s + 192;  // 16
    float* sW2D = s + 208;  // 144
    float* sb2D = s + 352;  // 9
    float* sW1P = s + 361;  // 192
    float* sb1P = s + 553;  // 16
    float* skD  = s + 569;  // 9
    float* sc   = s + 578;  // 8
    int t = threadIdx.x;
    if (t < 192) { sW1D[t] = W1D[t]; sW1P[t] = W1P[t]; }
    if (t < 16)  { sb1D[t] = b1D[t]; sb1P[t] = b1P[t]; }
    if (t < 144) sW2D[t] = W2D[t];
    if (t < 9)   { sb2D[t] = b2D[t]; skD[t] = kernel_D[t]; }
    if (t < 8)   sc[t] = c[t];
    __syncthreads();

    int l = blockIdx.x * 256 + t;
    int h = l >> 7, w = l & 127;
    float feat[12];
    feat[0] = (float)h * (1.0f / 128.0f);  // meshgrid 'ij' quirk -> first coord is h/W
    feat[1] = 1.0f - feat[0];
    feat[2] = (float)w * (1.0f / 128.0f);
    feat[3] = 1.0f - feat[2];
#pragma unroll
    for (int j = 0; j < 8; j++) feat[4 + j] = sc[j];

    // depthwise branch
    float hD[16];
#pragma unroll
    for (int j = 0; j < 16; j++) {
        float a = sb1D[j];
#pragma unroll
        for (int f = 0; f < 12; f++) a += feat[f] * sW1D[f * 16 + j];
        hD[j] = fmaxf(a, 0.0f);
    }
#pragma unroll
    for (int k = 0; k < 9; k++) {
        float a = skD[k] + sb2D[k];
#pragma unroll
        for (int j = 0; j < 16; j++) a += hD[j] * sW2D[j * 9 + k];
        g_kD[l * 9 + k] = a;
    }
    // pointwise branch hidden vector
#pragma unroll
    for (int j = 0; j < 16; j++) {
        float a = sb1P[j];
#pragma unroll
        for (int f = 0; f < 12; f++) a += feat[f] * sW1P[f * 16 + j];
        g_hP[l * 16 + j] = fmaxf(a, 0.0f);
    }
}

// ---------------- main fused kernel ----------------
// smem layout (floats)
#define SM_W2PT 0          // 16384  : [h][o*32+i]
#define SM_KP0T 16384      // 1024   : [o*32+i]
#define SM_KP   17408      // 4*1152 : [ll][o*36+i]  (padded rows)
#define SM_Y    22016      // 4*288  : [ll][b*36+i]
#define SM_HPT  23168      // 256    : [g][h][ll]
#define SM_KD   23424      // 144    : [ll16][k]
#define SM_OUT  23568      // 256*17 : [t][lloc]
#define SM_FLOATS 27920    // 111680 bytes

extern __shared__ float sm[];

__global__ void __launch_bounds__(256, 2)
k_main(const float* __restrict__ bias, float* __restrict__ out) {
    int t = threadIdx.x;
    int bx = blockIdx.x;          // 1024 blocks: 128 rows x 8 tiles of 16
    int h = bx >> 3;
    int w0 = (bx & 7) << 4;
    int l0 = h * 128 + w0;

    // cooperative loads
    {
        float4* d = (float4*)(sm + SM_W2PT);
        const float4* srcp = (const float4*)g_W2Pt;
#pragma unroll
        for (int it = 0; it < 16; it++) d[t + 256 * it] = srcp[t + 256 * it];
        ((float4*)(sm + SM_KP0T))[t] = ((const float4*)g_kP0t)[t];
        int g = t >> 6, hh = (t >> 2) & 15, ll = t & 3;
        sm[SM_HPT + g * 64 + hh * 4 + ll] = g_hP[(l0 + g * 4 + ll) * 16 + hh];
        if (t < 144) sm[SM_KD + t] = g_kD[l0 * 9 + t];
    }
    float bias_r = __ldg(&bias[t & 31]);

    // sliding 3x6 register column window of xTp (reused across the 4 groups)
    float col[3][6];
#pragma unroll
    for (int kh = 0; kh < 3; kh++)
#pragma unroll
        for (int cc = 0; cc < 6; cc++)
            col[kh][cc] = g_xTp[((h + kh) * 130 + w0 + cc) * 256 + t];

    __syncthreads();

    for (int g = 0; g < 4; g++) {
        // ---- Stage Y: depthwise for 4 locations, thread = (b = t>>5, i = t&31) ----
#pragma unroll
        for (int ll = 0; ll < 4; ll++) {
            const float* kd = &sm[SM_KD + (4 * g + ll) * 9];
            float y = 0.0f;
#pragma unroll
            for (int kh = 0; kh < 3; kh++)
#pragma unroll
                for (int kw = 0; kw < 3; kw++)
                    y += col[kh][ll + kw] * kd[kh * 3 + kw];
            sm[SM_Y + ll * 288 + (t >> 5) * 36 + (t & 31)] = y;
        }
        // shift window left by 4, prefetch 4 new columns (overlaps with stages A/B)
        if (g < 3) {
            int wnew = w0 + 4 * (g + 1);
#pragma unroll
            for (int kh = 0; kh < 3; kh++) {
                col[kh][0] = col[kh][4];
                col[kh][1] = col[kh][5];
#pragma unroll
                for (int cc = 2; cc < 6; cc++)
                    col[kh][cc] = g_xTp[((h + kh) * 130 + wnew + cc) * 256 + t];
            }
        }
        // ---- Stage A: build kP for 4 locations, thread = (o = t>>3, i = (t&7)*4) ----
        {
            int o = t >> 3, ib = (t & 7) << 2;
            float4 k0 = *(const float4*)&sm[SM_KP0T + o * 32 + ib];
            float4 a0 = k0, a1 = k0, a2 = k0, a3 = k0;
#pragma unroll
            for (int hh = 0; hh < 16; hh++) {
                float4 hv = *(const float4*)&sm[SM_HPT + g * 64 + hh * 4];
                float4 wv = *(const float4*)&sm[SM_W2PT + hh * 1024 + o * 32 + ib];
                a0.x += hv.x * wv.x; a0.y += hv.x * wv.y; a0.z += hv.x * wv.z; a0.w += hv.x * wv.w;
                a1.x += hv.y * wv.x; a1.y += hv.y * wv.y; a1.z += hv.y * wv.z; a1.w += hv.y * wv.w;
                a2.x += hv.z * wv.x; a2.y += hv.z * wv.y; a2.z += hv.z * wv.z; a2.w += hv.z * wv.w;
                a3.x += hv.w * wv.x; a3.y += hv.w * wv.y; a3.z += hv.w * wv.z; a3.w += hv.w * wv.w;
            }
            *(float4*)&sm[SM_KP + 0 * 1152 + o * 36 + ib] = a0;
            *(float4*)&sm[SM_KP + 1 * 1152 + o * 36 + ib] = a1;
            *(float4*)&sm[SM_KP + 2 * 1152 + o * 36 + ib] = a2;
            *(float4*)&sm[SM_KP + 3 * 1152 + o * 36 + ib] = a3;
        }
        __syncthreads();
        // ---- Stage B: out[b,o] = bias + y . kP, thread = (b = t>>5, o = t&31) ----
        {
            int b = t >> 5, oo = t & 31;
#pragma unroll
            for (int ll = 0; ll < 4; ll++) {
                float acc = bias_r;
#pragma unroll
                for (int i4 = 0; i4 < 8; i4++) {
                    float4 yv = *(const float4*)&sm[SM_Y + ll * 288 + b * 36 + i4 * 4];
                    float4 kv = *(const float4*)&sm[SM_KP + ll * 1152 + oo * 36 + i4 * 4];
                    acc += yv.x * kv.x + yv.y * kv.y + yv.z * kv.z + yv.w * kv.w;
                }
                sm[SM_OUT + t * 17 + g * 4 + ll] = acc;
            }
        }
        __syncthreads();
    }

    // ---- coalesced final store: rows r = (b*32+o), 16 cols each ----
    int lane = t & 31, wi = t >> 5;
#pragma unroll
    for (int it = 0; it < 16; it++) {
        int r = wi * 32 + it * 2 + (lane >> 4);
        int cc = lane & 15;
        out[r * 16384 + l0 + cc] = sm[SM_OUT + r * 17 + cc];
    }
}

// ---------------- launch ----------------
extern "C" void kernel_launch(void* const* d_in, const int* in_sizes, int n_in,
                              void* d_out, int out_size) {
    (void)in_sizes; (void)n_in; (void)out_size;
    const float* x        = (const float*)d_in[0];
    const float* kernel_D = (const float*)d_in[1];
    const float* kernel_P = (const float*)d_in[2];
    const float* bias     = (const float*)d_in[3];
    const float* c        = (const float*)d_in[4];
    const float* W1D      = (const float*)d_in[5];
    const float* b1D      = (const float*)d_in[6];
    const float* W2D      = (const float*)d_in[7];
    const float* b2D      = (const float*)d_in[8];
    const float* W1P      = (const float*)d_in[9];
    const float* b1P      = (const float*)d_in[10];
    const float* W2P      = (const float*)d_in[11];
    const float* b2P      = (const float*)d_in[12];
    float* out = (float*)d_out;

    cudaFuncSetAttribute(k_main, cudaFuncAttributeMaxDynamicSharedMemorySize,
                         SM_FLOATS * sizeof(float));

    k_border<<<516, 256>>>();
    k_transpose<<<dim3(512, 8), 256>>>(x);
    k_prep<<<1, 256>>>(kernel_P, W2P, b2P);
    k_mlp<<<64, 256>>>(kernel_D, c, W1D, b1D, W2D, b2D, W1P, b1P);
    k_main<<<1024, 256, SM_FLOATS * sizeof(float)>>>(bias, out);
}

// round 3
// speedup vs baseline: 1.1102x; 1.1102x over previous
#include <cuda_runtime.h>

#define L_TOT 16384

// ---------------- device scratch ----------------
__device__ float g_xTp[130 * 130 * 256];   // padded, location-major x: [hp][wp][b*32+i]
__device__ float g_hP[L_TOT * 16];         // per-location hidden vector (pointwise MLP)
__device__ float g_kD[L_TOT * 9];          // per-location depthwise 3x3 kernel
__device__ float g_W2Pt[16 * 1024];        // W2P transposed: [h][o*32+i]
__device__ float g_kP0t[1024];             // (kernel_P + b2P) transposed: [o*32+i]

// ---------------- kernel: border-zero + weight prep (merged) ----------------
__global__ void k_pre(const float* __restrict__ kernel_P,
                      const float* __restrict__ W2P,
                      const float* __restrict__ b2P) {
    int bid = blockIdx.x;
    int t = threadIdx.x;
    if (bid < 516) {
        int hp, wp;
        if (bid < 130)      { hp = 0;             wp = bid; }
        else if (bid < 260) { hp = 129;           wp = bid - 130; }
        else if (bid < 388) { hp = bid - 260 + 1; wp = 0; }
        else                { hp = bid - 388 + 1; wp = 129; }
        g_xTp[(hp * 130 + wp) * 256 + t] = 0.0f;
    } else {
        for (int idx = t; idx < 16384; idx += 256) {
            int hh = idx >> 10, rem = idx & 1023;
            int o = rem >> 5, i = rem & 31;
            g_W2Pt[idx] = W2P[hh * 1024 + i * 32 + o];
        }
        for (int idx = t; idx < 1024; idx += 256) {
            int o = idx >> 5, i = idx & 31;
            g_kP0t[idx] = kernel_P[i * 32 + o] + b2P[i * 32 + o];
        }
    }
}

// ---------------- kernel: tiled transpose x(BC,HW) -> xTp(HW_padded, BC) ----------------
__global__ void k_transpose(const float* __restrict__ x) {
    __shared__ float tile[32][33];
    int tx = threadIdx.x & 31, ty = threadIdx.x >> 5;
    int hw0 = blockIdx.x * 32;
    int bc0 = blockIdx.y * 32;
#pragma unroll
    for (int j = 0; j < 4; j++) {
        int bc = bc0 + ty + 8 * j;
        tile[ty + 8 * j][tx] = x[bc * L_TOT + hw0 + tx];
    }
    __syncthreads();
#pragma unroll
    for (int j = 0; j < 4; j++) {
        int rr = ty + 8 * j;
        int hw = hw0 + rr;
        int h = hw >> 7, w = hw & 127;
        g_xTp[((h + 1) * 130 + (w + 1)) * 256 + bc0 + tx] = tile[tx][rr];
    }
}

// ---------------- kernel: per-location MLPs -> hP, kD (wide grid) ----------------
__global__ void k_mlp(const float* __restrict__ kernel_D,
                      const float* __restrict__ c,
                      const float* __restrict__ W1D, const float* __restrict__ b1D,
                      const float* __restrict__ W2D, const float* __restrict__ b2D,
                      const float* __restrict__ W1P, const float* __restrict__ b1P) {
    __shared__ float s[586];
    float* sW1D = s;        // 192
    float* sb1D = s + 192;  // 16
    float* sW2D = s + 208;  // 144
    float* sb2D = s + 352;  // 9
    float* sW1P = s + 361;  // 192
    float* sb1P = s + 553;  // 16
    float* skD  = s + 569;  // 9
    float* sc   = s + 578;  // 8
    int t = threadIdx.x;   // 32 threads
    for (int i = t; i < 192; i += 32) { sW1D[i] = W1D[i]; sW1P[i] = W1P[i]; }
    for (int i = t; i < 144; i += 32) sW2D[i] = W2D[i];
    if (t < 16) { sb1D[t] = b1D[t]; sb1P[t] = b1P[t]; }
    if (t < 9)  { sb2D[t] = b2D[t]; skD[t] = kernel_D[t]; }
    if (t < 8)  sc[t] = c[t];
    __syncwarp();

    int l = blockIdx.x * 32 + t;
    int h = l >> 7, w = l & 127;
    float feat[12];
    feat[0] = (float)h * (1.0f / 128.0f);  // meshgrid 'ij' quirk -> first coord is h/W
    feat[1] = 1.0f - feat[0];
    feat[2] = (float)w * (1.0f / 128.0f);
    feat[3] = 1.0f - feat[2];
#pragma unroll
    for (int j = 0; j < 8; j++) feat[4 + j] = sc[j];

    float hD[16];
#pragma unroll
    for (int j = 0; j < 16; j++) {
        float a = sb1D[j];
#pragma unroll
        for (int f = 0; f < 12; f++) a += feat[f] * sW1D[f * 16 + j];
        hD[j] = fmaxf(a, 0.0f);
    }
#pragma unroll
    for (int k = 0; k < 9; k++) {
        float a = skD[k] + sb2D[k];
#pragma unroll
        for (int j = 0; j < 16; j++) a += hD[j] * sW2D[j * 9 + k];
        g_kD[l * 9 + k] = a;
    }
#pragma unroll
    for (int j = 0; j < 16; j++) {
        float a = sb1P[j];
#pragma unroll
        for (int f = 0; f < 12; f++) a += feat[f] * sW1P[f * 16 + j];
        g_hP[l * 16 + j] = fmaxf(a, 0.0f);
    }
}

// ---------------- main fused kernel: 512 threads, 32-wide tile per CTA ----------------
// smem layout (floats)
#define SM_W2PT 0          // 16384 : [h][o*32+i]
#define SM_KP0T 16384      // 1024  : [o*32+i]
#define SM_KP   17408      // 2*8*1152 = 18432 : [half][ll][o*36+i]
#define SM_Y    35840      // 2*8*288  = 4608  : [half][ll][b*36+i]
#define SM_HPT  40448      // 2*2*16*8 = 512   : [half][g][hh][ll]
#define SM_KD   40960      // 32*9 = 288       : [loc][k]
#define SM_OUT  41248      // 256*33 = 8448    : [b*32+o][col] (pad 33)
#define SM_FLOATS 49696    // 198784 bytes

extern __shared__ float sm[];

__global__ void __launch_bounds__(512, 1)
k_main(const float* __restrict__ bias, float* __restrict__ out) {
    int t = threadIdx.x;
    int bx = blockIdx.x;           // 512 blocks: 128 rows x 4 tiles of 32
    int h = bx >> 2;
    int w0 = (bx & 3) << 5;
    int l0 = h * 128 + w0;
    int half = t >> 8, tt = t & 255;
    int wbase = w0 + (half << 4);

    // cooperative loads
    {
        float4* d = (float4*)(sm + SM_W2PT);
        const float4* s4 = (const float4*)g_W2Pt;
#pragma unroll
        for (int it = 0; it < 8; it++) d[t + 512 * it] = s4[t + 512 * it];
        if (t < 256) ((float4*)(sm + SM_KP0T))[t] = ((const float4*)g_kP0t)[t];
        int hf = t >> 8, g2 = (t >> 7) & 1, hh = (t >> 3) & 15, ll = t & 7;
        sm[SM_HPT + hf * 256 + g2 * 128 + hh * 8 + ll] =
            g_hP[(h * 128 + w0 + hf * 16 + g2 * 8 + ll) * 16 + hh];
        if (t < 288) sm[SM_KD + t] = g_kD[l0 * 9 + t];
    }
    float bias_r = __ldg(&bias[t & 31]);

    // 3x10 sliding register window of xTp (covers 8 locations per group)
    float col[3][10];
#pragma unroll
    for (int kh = 0; kh < 3; kh++)
#pragma unroll
        for (int cc = 0; cc < 10; cc++)
            col[kh][cc] = g_xTp[((h + kh) * 130 + wbase + cc) * 256 + tt];

    __syncthreads();

#pragma unroll
    for (int g = 0; g < 2; g++) {
        // ---- Stage Y: depthwise, 8 locations; thread = (half, b=tt>>5, i=tt&31) ----
        {
            int b = tt >> 5, ii = tt & 31;
#pragma unroll
            for (int ll = 0; ll < 8; ll++) {
                const float* kd = &sm[SM_KD + (half * 16 + g * 8 + ll) * 9];
                float y = 0.0f;
#pragma unroll
                for (int kh = 0; kh < 3; kh++)
#pragma unroll
                    for (int kw = 0; kw < 3; kw++)
                        y += col[kh][ll + kw] * kd[kh * 3 + kw];
                sm[SM_Y + half * 2304 + ll * 288 + b * 36 + ii] = y;
            }
            if (g == 0) {   // shift window by 8, prefetch next 8 columns
#pragma unroll
                for (int kh = 0; kh < 3; kh++) {
                    col[kh][0] = col[kh][8];
                    col[kh][1] = col[kh][9];
#pragma unroll
                    for (int cc = 2; cc < 10; cc++)
                        col[kh][cc] = g_xTp[((h + kh) * 130 + wbase + 8 + cc) * 256 + tt];
                }
            }
        }
        // ---- Stage A: build kP for 8 locations; thread = (half, o=(t>>3)&31, ib=(t&7)*4) ----
        {
            int o = (t >> 3) & 31, ib = (t & 7) << 2;
            float4 k0 = *(const float4*)&sm[SM_KP0T + o * 32 + ib];
            float4 a0 = k0, a1 = k0, a2 = k0, a3 = k0, a4 = k0, a5 = k0, a6 = k0, a7 = k0;
            const float* hpt = &sm[SM_HPT + half * 256 + g * 128];
#pragma unroll
            for (int hh = 0; hh < 16; hh++) {
                float4 h0 = *(const float4*)&hpt[hh * 8];
                float4 h1 = *(const float4*)&hpt[hh * 8 + 4];
                float4 wv = *(const float4*)&sm[SM_W2PT + hh * 1024 + o * 32 + ib];
                a0.x += h0.x * wv.x; a0.y += h0.x * wv.y; a0.z += h0.x * wv.z; a0.w += h0.x * wv.w;
                a1.x += h0.y * wv.x; a1.y += h0.y * wv.y; a1.z += h0.y * wv.z; a1.w += h0.y * wv.w;
                a2.x += h0.z * wv.x; a2.y += h0.z * wv.y; a2.z += h0.z * wv.z; a2.w += h0.z * wv.w;
                a3.x += h0.w * wv.x; a3.y += h0.w * wv.y; a3.z += h0.w * wv.z; a3.w += h0.w * wv.w;
                a4.x += h1.x * wv.x; a4.y += h1.x * wv.y; a4.z += h1.x * wv.z; a4.w += h1.x * wv.w;
                a5.x += h1.y * wv.x; a5.y += h1.y * wv.y; a5.z += h1.y * wv.z; a5.w += h1.y * wv.w;
                a6.x += h1.z * wv.x; a6.y += h1.z * wv.y; a6.z += h1.z * wv.z; a6.w += h1.z * wv.w;
                a7.x += h1.w * wv.x; a7.y += h1.w * wv.y; a7.z += h1.w * wv.z; a7.w += h1.w * wv.w;
            }
            float* kp = &sm[SM_KP + half * 9216 + o * 36 + ib];
            *(float4*)&kp[0 * 1152] = a0; *(float4*)&kp[1 * 1152] = a1;
            *(float4*)&kp[2 * 1152] = a2; *(float4*)&kp[3 * 1152] = a3;
            *(float4*)&kp[4 * 1152] = a4; *(float4*)&kp[5 * 1152] = a5;
            *(float4*)&kp[6 * 1152] = a6; *(float4*)&kp[7 * 1152] = a7;
        }
        __syncthreads();
        // ---- Stage B: out = bias + y . kP; thread = (half, bh, sub, o), 2 b's each ----
        {
            int bh = (t >> 6) & 3, sub = (t >> 5) & 1, o = t & 31;
            int b0 = bh * 2, b1 = b0 + 1;
            const float* Yh = &sm[SM_Y + half * 2304];
            const float* KPh = &sm[SM_KP + half * 9216];
#pragma unroll
            for (int llq = 0; llq < 4; llq++) {
                int ll = sub * 4 + llq;
                float acc0 = bias_r, acc1 = bias_r;
#pragma unroll
                for (int i4 = 0; i4 < 8; i4++) {
                    float4 kv = *(const float4*)&KPh[ll * 1152 + o * 36 + i4 * 4];
                    float4 y0 = *(const float4*)&Yh[ll * 288 + b0 * 36 + i4 * 4];
                    float4 y1 = *(const float4*)&Yh[ll * 288 + b1 * 36 + i4 * 4];
                    acc0 += y0.x * kv.x + y0.y * kv.y + y0.z * kv.z + y0.w * kv.w;
                    acc1 += y1.x * kv.x + y1.y * kv.y + y1.z * kv.z + y1.w * kv.w;
                }
                int colx = half * 16 + g * 8 + ll;
                sm[SM_OUT + (b0 * 32 + o) * 33 + colx] = acc0;
                sm[SM_OUT + (b1 * 32 + o) * 33 + colx] = acc1;
            }
        }
        __syncthreads();
    }

    // ---- coalesced final store: 256 rows x 32 cols; thread -> (row, 16-col half) ----
    {
        int r = t >> 1;
        int cst = (t & 1) << 4;
        const float* src = &sm[SM_OUT + r * 33 + cst];
        float* dst = &out[r * 16384 + l0 + cst];
#pragma unroll
        for (int j = 0; j < 4; j++) {
            float4 v;
            v.x = src[j * 4 + 0]; v.y = src[j * 4 + 1];
            v.z = src[j * 4 + 2]; v.w = src[j * 4 + 3];
            *(float4*)&dst[j * 4] = v;
        }
    }
}

// ---------------- launch ----------------
extern "C" void kernel_launch(void* const* d_in, const int* in_sizes, int n_in,
                              void* d_out, int out_size) {
    (void)in_sizes; (void)n_in; (void)out_size;
    const float* x        = (const float*)d_in[0];
    const float* kernel_D = (const float*)d_in[1];
    const float* kernel_P = (const float*)d_in[2];
    const float* bias     = (const float*)d_in[3];
    const float* c        = (const float*)d_in[4];
    const float* W1D      = (const float*)d_in[5];
    const float* b1D      = (const float*)d_in[6];
    const float* W2D      = (const float*)d_in[7];
    const float* b2D      = (const float*)d_in[8];
    const float* W1P      = (const float*)d_in[9];
    const float* b1P      = (const float*)d_in[10];
    const float* W2P      = (const float*)d_in[11];
    const float* b2P      = (const float*)d_in[12];
    float* out = (float*)d_out;

    cudaFuncSetAttribute(k_main, cudaFuncAttributeMaxDynamicSharedMemorySize,
                         SM_FLOATS * sizeof(float));

    k_pre<<<517, 256>>>(kernel_P, W2P, b2P);
    k_transpose<<<dim3(512, 8), 256>>>(x);
    k_mlp<<<512, 32>>>(kernel_D, c, W1D, b1D, W2D, b2D, W1P, b1P);
    k_main<<<512, 512, SM_FLOATS * sizeof(float)>>>(bias, out);
}